// round 1
// baseline (speedup 1.0000x reference)
#include <cuda_runtime.h>
#include <cstdint>

#define BATCH 8
#define SEQ   2048
#define EMBED 1024
#define HEAD  64

#define BM 64      // query rows / projection rows per block
#define BK 32      // projection K-chunk
#define BN 64      // key tile

__device__ float g_q[BATCH * SEQ * HEAD];
__device__ float g_k[BATCH * SEQ * HEAD];
__device__ float g_v[BATCH * SEQ * HEAD];

__device__ __forceinline__ float neg_inf() { return __int_as_float(0xff800000); }

// ---------------------------------------------------------------------------
// Kernel A: fused QKV projection.
// Block = 64 rows of one batch, computes all 192 output columns (Q|K|V).
// Thread tile: 8 rows x 6 cols, K-chunks of 32, float4 smem loads.
// Q is pre-scaled by 1/sqrt(HEAD) = 0.125.
// ---------------------------------------------------------------------------
__global__ __launch_bounds__(256) void proj_kernel(
    const float* __restrict__ emb,
    const float* __restrict__ Wq,
    const float* __restrict__ Wk,
    const float* __restrict__ Wv)
{
    __shared__ float e_s[BM][BK];          // 64 x 32
    __shared__ float w_s[192][BK + 4];     // transposed W tile [col][kk], pitch 36

    const int tile = blockIdx.x;           // 0..255
    const int b    = tile >> 5;            // /32
    const int row0 = (tile & 31) * BM;
    const int tid  = threadIdx.x;
    const int tx   = tid & 31;
    const int ty   = tid >> 5;

    float acc[8][6];
#pragma unroll
    for (int i = 0; i < 8; i++)
#pragma unroll
        for (int j = 0; j < 6; j++) acc[i][j] = 0.f;

    const float* ebase = emb + ((size_t)b * SEQ + row0) * EMBED;

    for (int k0 = 0; k0 < EMBED; k0 += BK) {
        // load 64x32 embedding tile (coalesced)
        {
            const int r  = tid >> 5;   // 0..7
            const int kk = tid & 31;
#pragma unroll
            for (int i = 0; i < 8; i++)
                e_s[r + 8 * i][kk] = ebase[(size_t)(r + 8 * i) * EMBED + k0 + kk];
        }
        // load 32x64 tiles of Wq/Wk/Wv, transposed into [col][kk]
#pragma unroll
        for (int it = 0; it < 8; it++) {
            const int idx = tid + 256 * it;     // 0..2047
            const int kk  = idx >> 6;
            const int col = idx & 63;
            const int gw  = (k0 + kk) * HEAD + col;
            w_s[col][kk]       = Wq[gw];
            w_s[64 + col][kk]  = Wk[gw];
            w_s[128 + col][kk] = Wv[gw];
        }
        __syncthreads();

#pragma unroll
        for (int kk = 0; kk < BK; kk += 4) {
            float4 a[8], bb[6];
#pragma unroll
            for (int i = 0; i < 8; i++)
                a[i] = *(const float4*)&e_s[ty + 8 * i][kk];
#pragma unroll
            for (int j = 0; j < 6; j++)
                bb[j] = *(const float4*)&w_s[tx + 32 * j][kk];
#pragma unroll
            for (int i = 0; i < 8; i++) {
#pragma unroll
                for (int j = 0; j < 6; j++) {
                    acc[i][j] += a[i].x * bb[j].x;
                    acc[i][j] += a[i].y * bb[j].y;
                    acc[i][j] += a[i].z * bb[j].z;
                    acc[i][j] += a[i].w * bb[j].w;
                }
            }
        }
        __syncthreads();
    }

#pragma unroll
    for (int i = 0; i < 8; i++) {
        const size_t rowoff = ((size_t)b * SEQ + row0 + ty + 8 * i) * HEAD;
        g_q[rowoff + tx]      = acc[i][0] * 0.125f;   // 1/sqrt(64) baked into Q
        g_q[rowoff + tx + 32] = acc[i][1] * 0.125f;
        g_k[rowoff + tx]      = acc[i][2];
        g_k[rowoff + tx + 32] = acc[i][3];
        g_v[rowoff + tx]      = acc[i][4];
        g_v[rowoff + tx + 32] = acc[i][5];
    }
}

// ---------------------------------------------------------------------------
// Kernel B: causal flash attention, fp32.
// Block = 64 queries of one batch. 8 warps, each warp owns 8 query rows.
// Lane owns key columns {lane, lane+32} (scores) and head dims {lane, lane+32}
// (output accumulators). K stored [k][d] pitch 68, V stored [h][k] pitch 68 ->
// conflict-free float4 LDS everywhere.
// ---------------------------------------------------------------------------
__global__ __launch_bounds__(256) void attn_kernel(float* __restrict__ out)
{
    extern __shared__ float sm[];
    float(*q_s)[64] = (float(*)[64])sm;                           // 64x64
    float(*k_s)[68] = (float(*)[68])(sm + 64 * 64);               // [k][d]
    float(*v_s)[68] = (float(*)[68])(sm + 64 * 64 + 64 * 68);     // [h][k]
    float(*p_s)[64] = (float(*)[64])(sm + 64 * 64 + 2 * 64 * 68); // [r][k]

    const int b    = blockIdx.x >> 5;
    const int qt   = (SEQ / BM - 1) - (blockIdx.x & 31);  // heavy tiles first
    const int qbase = qt * BM;
    const int tid  = threadIdx.x;
    const int lane = tid & 31;
    const int w    = tid >> 5;
    const int rows0 = w * 8;

    const float* qg  = g_q + ((size_t)b * SEQ + qbase) * HEAD;
    const float* kgl = g_k + (size_t)b * SEQ * HEAD;
    const float* vgl = g_v + (size_t)b * SEQ * HEAD;

    // load Q tile
    {
        const int r = tid >> 6;   // 0..3
        const int d = tid & 63;
#pragma unroll
        for (int i = 0; i < 64; i += 4)
            q_s[r + i][d] = qg[(size_t)(r + i) * HEAD + d];
    }

    float m_r[8], l_r[8], acc[8][2];
#pragma unroll
    for (int r = 0; r < 8; r++) {
        m_r[r] = neg_inf();
        l_r[r] = 0.f;
        acc[r][0] = 0.f;
        acc[r][1] = 0.f;
    }

    for (int kt = 0; kt <= qt; kt++) {
        __syncthreads();   // covers Q load on first iter, K/V reuse after
        {
            const int r = tid >> 6;
            const int c = tid & 63;
            const float* kp = kgl + (size_t)kt * BN * HEAD;
            const float* vp = vgl + (size_t)kt * BN * HEAD;
#pragma unroll
            for (int i = 0; i < 64; i += 4) {
                const float kv = kp[(size_t)(r + i) * HEAD + c];
                const float vv = vp[(size_t)(r + i) * HEAD + c];
                k_s[r + i][c] = kv;      // [k][d]
                v_s[c][r + i] = vv;      // transpose -> [h][k]
            }
        }
        __syncthreads();

        const bool diag = (kt == qt);

        // ---- scores + online softmax (per-warp rows) ----
#pragma unroll
        for (int r = 0; r < 8; r++) {
            float s0 = 0.f, s1 = 0.f;
#pragma unroll
            for (int d = 0; d < 64; d += 4) {
                const float4 qv = *(const float4*)&q_s[rows0 + r][d];
                const float4 k0 = *(const float4*)&k_s[lane][d];
                const float4 k1 = *(const float4*)&k_s[lane + 32][d];
                s0 += qv.x * k0.x; s1 += qv.x * k1.x;
                s0 += qv.y * k0.y; s1 += qv.y * k1.y;
                s0 += qv.z * k0.z; s1 += qv.z * k1.z;
                s0 += qv.w * k0.w; s1 += qv.w * k1.w;
            }
            if (diag) {
                const int qrow = qbase + rows0 + r;
                if (kt * BN + lane > qrow)      s0 = neg_inf();
                if (kt * BN + lane + 32 > qrow) s1 = neg_inf();
            }
            float tmax = fmaxf(s0, s1);
#pragma unroll
            for (int off = 16; off; off >>= 1)
                tmax = fmaxf(tmax, __shfl_xor_sync(0xffffffffu, tmax, off));
            const float mnew = fmaxf(m_r[r], tmax);
            const float p0 = __expf(s0 - mnew);
            const float p1 = __expf(s1 - mnew);
            const float corr = __expf(m_r[r] - mnew);
            float psum = p0 + p1;
#pragma unroll
            for (int off = 16; off; off >>= 1)
                psum += __shfl_xor_sync(0xffffffffu, psum, off);
            l_r[r] = l_r[r] * corr + psum;
            m_r[r] = mnew;
            acc[r][0] *= corr;
            acc[r][1] *= corr;
            p_s[rows0 + r][lane]      = p0;
            p_s[rows0 + r][lane + 32] = p1;
        }
        __syncwarp();   // p_s is per-warp; make lane writes visible

        // ---- P @ V ----
#pragma unroll
        for (int k4 = 0; k4 < 64; k4 += 4) {
            const float4 v0 = *(const float4*)&v_s[lane][k4];
            const float4 v1 = *(const float4*)&v_s[lane + 32][k4];
#pragma unroll
            for (int r = 0; r < 8; r++) {
                const float4 pv = *(const float4*)&p_s[rows0 + r][k4];
                acc[r][0] += pv.x * v0.x; acc[r][1] += pv.x * v1.x;
                acc[r][0] += pv.y * v0.y; acc[r][1] += pv.y * v1.y;
                acc[r][0] += pv.z * v0.z; acc[r][1] += pv.z * v1.z;
                acc[r][0] += pv.w * v0.w; acc[r][1] += pv.w * v1.w;
            }
        }
        __syncwarp();   // p_s reads done before next tile rewrites it
    }

    float* ob = out + ((size_t)b * SEQ + qbase) * HEAD;
#pragma unroll
    for (int r = 0; r < 8; r++) {
        const float inv = 1.f / l_r[r];
        ob[(size_t)(rows0 + r) * HEAD + lane]      = acc[r][0] * inv;
        ob[(size_t)(rows0 + r) * HEAD + lane + 32] = acc[r][1] * inv;
    }
}

// ---------------------------------------------------------------------------
extern "C" void kernel_launch(void* const* d_in, const int* in_sizes, int n_in,
                              void* d_out, int out_size)
{
    (void)in_sizes; (void)n_in; (void)out_size;
    const float* emb = (const float*)d_in[0];
    const float* Wq  = (const float*)d_in[1];
    const float* Wk  = (const float*)d_in[2];
    const float* Wv  = (const float*)d_in[3];
    float* out = (float*)d_out;

    proj_kernel<<<BATCH * (SEQ / BM), 256>>>(emb, Wq, Wk, Wv);

    const size_t smem = (64 * 64 + 2 * 64 * 68 + 64 * 64) * sizeof(float); // 67584 B
    cudaFuncSetAttribute(attn_kernel, cudaFuncAttributeMaxDynamicSharedMemorySize,
                         (int)smem);
    attn_kernel<<<BATCH * (SEQ / BM), 256, smem>>>(out);
}

// round 3
// speedup vs baseline: 1.1700x; 1.1700x over previous
#include <cuda_runtime.h>
#include <cuda_bf16.h>
#include <cstdint>

#define BATCH 8
#define SEQ   2048
#define EMBED 1024
#define HEAD  64

#define BM 64      // attention query tile
#define BN 64      // attention key tile

// ---------------- device scratch ----------------
__device__ float g_q[BATCH * SEQ * HEAD];
__device__ float g_k[BATCH * SEQ * HEAD];
__device__ float g_v[BATCH * SEQ * HEAD];

__device__ __nv_bfloat16 g_ehi[BATCH * SEQ * EMBED];
__device__ __nv_bfloat16 g_elo[BATCH * SEQ * EMBED];
__device__ __nv_bfloat16 g_bhi[3 * HEAD * EMBED];   // [192][1024], B[n][k] = W(k, n%64)
__device__ __nv_bfloat16 g_blo[3 * HEAD * EMBED];

__device__ __forceinline__ float neg_inf() { return __int_as_float(0xff800000); }

__device__ __forceinline__ uint32_t smem_u32(const void* p) {
    uint32_t a;
    asm("{ .reg .u64 t; cvta.to.shared.u64 t, %1; cvt.u32.u64 %0, t; }" : "=r"(a) : "l"(p));
    return a;
}

// ---------------------------------------------------------------------------
// Kernel 1: fp32 -> bf16 hi/lo split of embeddings
// ---------------------------------------------------------------------------
__global__ __launch_bounds__(256) void conv_e_kernel(const float* __restrict__ e)
{
    const size_t i = ((size_t)blockIdx.x * 256 + threadIdx.x) * 4;
    const float4 x = *(const float4*)(e + i);
    __nv_bfloat16 h0 = __float2bfloat16_rn(x.x), h1 = __float2bfloat16_rn(x.y);
    __nv_bfloat16 h2 = __float2bfloat16_rn(x.z), h3 = __float2bfloat16_rn(x.w);
    __nv_bfloat16 l0 = __float2bfloat16_rn(x.x - __bfloat162float(h0));
    __nv_bfloat16 l1 = __float2bfloat16_rn(x.y - __bfloat162float(h1));
    __nv_bfloat16 l2 = __float2bfloat16_rn(x.z - __bfloat162float(h2));
    __nv_bfloat16 l3 = __float2bfloat16_rn(x.w - __bfloat162float(h3));
    __nv_bfloat162* hp = (__nv_bfloat162*)(g_ehi + i);
    __nv_bfloat162* lp = (__nv_bfloat162*)(g_elo + i);
    hp[0] = __halves2bfloat162(h0, h1);
    hp[1] = __halves2bfloat162(h2, h3);
    lp[0] = __halves2bfloat162(l0, l1);
    lp[1] = __halves2bfloat162(l2, l3);
}

// ---------------------------------------------------------------------------
// Kernel 2: build B[n][k] = W(k, n%64), n in [0,192), hi/lo bf16 split
// ---------------------------------------------------------------------------
__global__ __launch_bounds__(256) void conv_w_kernel(
    const float* __restrict__ Wq, const float* __restrict__ Wk, const float* __restrict__ Wv)
{
    const int idx = blockIdx.x * 256 + threadIdx.x;   // 192*1024 total
    const int n = idx >> 10, k = idx & 1023;
    const float* W = (n < 64) ? Wq : ((n < 128) ? Wk : Wv);
    const float x = W[k * HEAD + (n & 63)];
    const __nv_bfloat16 h = __float2bfloat16_rn(x);
    g_bhi[idx] = h;
    g_blo[idx] = __float2bfloat16_rn(x - __bfloat162float(h));
}

// ---------------------------------------------------------------------------
// Kernel 3: fused QKV projection via mma.sync (bf16, fp32 accum, 3-term hi/lo).
// CTA: 128 rows x 192 cols. 512 threads = 16 warps (4m x 4n), warp tile 32x48.
// K loop: 3 passes x 16 chunks of 64, cp.async double-buffered.
// ---------------------------------------------------------------------------
#define KCH   64            // k per chunk (bf16)
#define APITCH 72           // smem pitch in bf16 elements (144 B)
#define A_BYTES (128 * APITCH * 2)      // 18432
#define B_BYTES (192 * APITCH * 2)      // 27648
#define BUF_BYTES (A_BYTES + B_BYTES)   // 46080

__device__ __forceinline__ void cp16(uint32_t dst, const void* src) {
    asm volatile("cp.async.cg.shared.global [%0], [%1], 16;" :: "r"(dst), "l"(src) : "memory");
}
__device__ __forceinline__ void cp_commit() { asm volatile("cp.async.commit_group;" ::: "memory"); }
template <int N> __device__ __forceinline__ void cp_wait() {
    asm volatile("cp.async.wait_group %0;" :: "n"(N) : "memory");
}
__device__ __forceinline__ void ldm_x4(uint32_t (&r)[4], uint32_t addr) {
    asm volatile("ldmatrix.sync.aligned.m8n8.x4.shared.b16 {%0,%1,%2,%3}, [%4];"
                 : "=r"(r[0]), "=r"(r[1]), "=r"(r[2]), "=r"(r[3]) : "r"(addr));
}
__device__ __forceinline__ void mma_bf16(float (&d)[4], const uint32_t (&a)[4],
                                         uint32_t b0, uint32_t b1) {
    asm volatile(
        "mma.sync.aligned.m16n8k16.row.col.f32.bf16.bf16.f32 "
        "{%0,%1,%2,%3}, {%4,%5,%6,%7}, {%8,%9}, {%0,%1,%2,%3};"
        : "+f"(d[0]), "+f"(d[1]), "+f"(d[2]), "+f"(d[3])
        : "r"(a[0]), "r"(a[1]), "r"(a[2]), "r"(a[3]), "r"(b0), "r"(b1));
}

__global__ __launch_bounds__(512) void qkv_gemm_kernel()
{
    extern __shared__ char smg[];
    const int tid  = threadIdx.x;
    const int wid  = tid >> 5, lane = tid & 31;
    const int wm   = wid >> 2, wn = wid & 3;      // 4x4 warp grid
    const size_t row0 = (size_t)blockIdx.x * 128;

    const uint32_t smb = smem_u32(smg);

    float acc[2][6][4];
#pragma unroll
    for (int mi = 0; mi < 2; mi++)
#pragma unroll
        for (int nj = 0; nj < 6; nj++)
#pragma unroll
            for (int f = 0; f < 4; f++) acc[mi][nj][f] = 0.f;

    auto issue = [&](int c, int buf) {
        const int p  = c >> 4;
        const int k0 = (c & 15) * KCH;
        const __nv_bfloat16* As = (p == 1) ? g_elo : g_ehi;
        const __nv_bfloat16* Bs = (p == 2) ? g_blo : g_bhi;
        const uint32_t aBase = smb + buf * BUF_BYTES;
        const uint32_t bBase = aBase + A_BYTES;
        // A: 128 rows x 64 bf16 = 1024 x 16B, 2 per thread
#pragma unroll
        for (int j = 0; j < 2; j++) {
            const int idx = tid + 512 * j;
            const int r = idx >> 3, v = idx & 7;
            cp16(aBase + r * 144 + v * 16, As + (row0 + r) * (size_t)EMBED + k0 + v * 8);
        }
        // B: 192 rows x 64 bf16 = 1536 x 16B, 3 per thread
#pragma unroll
        for (int j = 0; j < 3; j++) {
            const int idx = tid + 512 * j;
            const int n = idx >> 3, v = idx & 7;
            cp16(bBase + n * 144 + v * 16, Bs + n * (size_t)EMBED + k0 + v * 8);
        }
        cp_commit();
    };

    issue(0, 0);

    for (int c = 0; c < 48; c++) {
        if (c < 47) {
            issue(c + 1, (c + 1) & 1);
            cp_wait<1>();
        } else {
            cp_wait<0>();
        }
        __syncthreads();

        const uint32_t aBase = smb + (c & 1) * BUF_BYTES;
        const uint32_t bBase = aBase + A_BYTES;

#pragma unroll
        for (int ks = 0; ks < 4; ks++) {        // k16 steps within chunk
            uint32_t a[2][4];
#pragma unroll
            for (int mi = 0; mi < 2; mi++) {
                const int row = wm * 32 + mi * 16 + (lane & 15);
                ldm_x4(a[mi], aBase + (uint32_t)(row * 144 + ks * 32 + (lane >> 4) * 16));
            }
            uint32_t bt[3][4];
#pragma unroll
            for (int nb = 0; nb < 3; nb++) {
                const int nrow = wn * 48 + nb * 16 + (lane & 7) + ((lane >> 4) << 3);
                const int koff = (lane >> 3) & 1;
                ldm_x4(bt[nb], bBase + (uint32_t)(nrow * 144 + ks * 32 + koff * 16));
            }
#pragma unroll
            for (int mi = 0; mi < 2; mi++)
#pragma unroll
                for (int nj = 0; nj < 6; nj++)
                    mma_bf16(acc[mi][nj], a[mi], bt[nj >> 1][(nj & 1) * 2],
                             bt[nj >> 1][(nj & 1) * 2 + 1]);
        }
        __syncthreads();
    }

    // Epilogue: write accumulators straight to g_q / g_k / g_v
    const int g = lane >> 2, t = lane & 3;
#pragma unroll
    for (int mi = 0; mi < 2; mi++) {
#pragma unroll
        for (int nj = 0; nj < 6; nj++) {
            const int colg = wn * 48 + nj * 8;          // 0..184, within one 64-group
            const int grp  = colg >> 6;
            const int nc   = (colg & 63) + 2 * t;
            float* dst = (grp == 0) ? g_q : ((grp == 1) ? g_k : g_v);
            const float s = (grp == 0) ? 0.125f : 1.0f;  // 1/sqrt(64) baked into Q
            const size_t r = row0 + wm * 32 + mi * 16 + g;
            float2 lo = make_float2(acc[mi][nj][0] * s, acc[mi][nj][1] * s);
            float2 hi = make_float2(acc[mi][nj][2] * s, acc[mi][nj][3] * s);
            *(float2*)&dst[r * HEAD + nc]       = lo;
            *(float2*)&dst[(r + 8) * HEAD + nc] = hi;
        }
    }
}

// ---------------------------------------------------------------------------
// Kernel 4: causal flash attention, fp32, k/v reused across rows.
// ---------------------------------------------------------------------------
__global__ __launch_bounds__(256, 2) void attn_kernel(float* __restrict__ out)
{
    extern __shared__ float smf[];
    float(*q_s)[64] = (float(*)[64])smf;
    float(*k_s)[68] = (float(*)[68])(smf + 64 * 64);
    float(*v_s)[68] = (float(*)[68])(smf + 64 * 64 + 64 * 68);
    float(*p_s)[64] = (float(*)[64])(smf + 64 * 64 + 2 * 64 * 68);

    const int b     = blockIdx.x >> 5;
    const int qt    = (SEQ / BM - 1) - (blockIdx.x & 31);  // heavy tiles first
    const int qbase = qt * BM;
    const int tid   = threadIdx.x;
    const int lane  = tid & 31;
    const int w     = tid >> 5;
    const int rows0 = w * 8;

    const float* qg  = g_q + ((size_t)b * SEQ + qbase) * HEAD;
    const float* kgl = g_k + (size_t)b * SEQ * HEAD;
    const float* vgl = g_v + (size_t)b * SEQ * HEAD;

    {
        const int r = tid >> 6;
        const int d = tid & 63;
#pragma unroll
        for (int i = 0; i < 64; i += 4)
            q_s[r + i][d] = qg[(size_t)(r + i) * HEAD + d];
    }

    float m_r[8], l_r[8], acc[8][2];
#pragma unroll
    for (int r = 0; r < 8; r++) {
        m_r[r] = neg_inf(); l_r[r] = 0.f; acc[r][0] = 0.f; acc[r][1] = 0.f;
    }

    for (int kt = 0; kt <= qt; kt++) {
        __syncthreads();
        {
            const int r = tid >> 6;
            const int c = tid & 63;
            const float* kp = kgl + (size_t)kt * BN * HEAD;
            const float* vp = vgl + (size_t)kt * BN * HEAD;
#pragma unroll
            for (int i = 0; i < 64; i += 4) {
                k_s[r + i][c] = kp[(size_t)(r + i) * HEAD + c];
                v_s[c][r + i] = vp[(size_t)(r + i) * HEAD + c];
            }
        }
        __syncthreads();

        const bool diag = (kt == qt);

        // scores: k loaded once per d-step, reused across all 8 rows
        float sc[8][2];
#pragma unroll
        for (int r = 0; r < 8; r++) { sc[r][0] = 0.f; sc[r][1] = 0.f; }
#pragma unroll
        for (int d = 0; d < 64; d += 4) {
            const float4 k0 = *(const float4*)&k_s[lane][d];
            const float4 k1 = *(const float4*)&k_s[lane + 32][d];
#pragma unroll
            for (int r = 0; r < 8; r++) {
                const float4 qv = *(const float4*)&q_s[rows0 + r][d];  // broadcast
                sc[r][0] += qv.x * k0.x; sc[r][1] += qv.x * k1.x;
                sc[r][0] += qv.y * k0.y; sc[r][1] += qv.y * k1.y;
                sc[r][0] += qv.z * k0.z; sc[r][1] += qv.z * k1.z;
                sc[r][0] += qv.w * k0.w; sc[r][1] += qv.w * k1.w;
            }
        }

#pragma unroll
        for (int r = 0; r < 8; r++) {
            float s0 = sc[r][0], s1 = sc[r][1];
            if (diag) {
                const int qrow = qbase + rows0 + r;
                if (kt * BN + lane > qrow)      s0 = neg_inf();
                if (kt * BN + lane + 32 > qrow) s1 = neg_inf();
            }
            float tmax = fmaxf(s0, s1);
#pragma unroll
            for (int off = 16; off; off >>= 1)
                tmax = fmaxf(tmax, __shfl_xor_sync(0xffffffffu, tmax, off));
            const float mnew = fmaxf(m_r[r], tmax);
            const float p0 = __expf(s0 - mnew);
            const float p1 = __expf(s1 - mnew);
            const float corr = __expf(m_r[r] - mnew);
            float psum = p0 + p1;
#pragma unroll
            for (int off = 16; off; off >>= 1)
                psum += __shfl_xor_sync(0xffffffffu, psum, off);
            l_r[r] = l_r[r] * corr + psum;
            m_r[r] = mnew;
            acc[r][0] *= corr;
            acc[r][1] *= corr;
            p_s[rows0 + r][lane]      = p0;
            p_s[rows0 + r][lane + 32] = p1;
        }
        __syncwarp();

        // P @ V: v loaded once per k-step, reused across rows
#pragma unroll
        for (int k4 = 0; k4 < 64; k4 += 4) {
            const float4 v0 = *(const float4*)&v_s[lane][k4];
            const float4 v1 = *(const float4*)&v_s[lane + 32][k4];
#pragma unroll
            for (int r = 0; r < 8; r++) {
                const float4 pv = *(const float4*)&p_s[rows0 + r][k4];  // broadcast
                acc[r][0] += pv.x * v0.x; acc[r][1] += pv.x * v1.x;
                acc[r][0] += pv.y * v0.y; acc[r][1] += pv.y * v1.y;
                acc[r][0] += pv.z * v0.z; acc[r][1] += pv.z * v1.z;
                acc[r][0] += pv.w * v0.w; acc[r][1] += pv.w * v1.w;
            }
        }
        __syncwarp();
    }

    float* ob = out + ((size_t)b * SEQ + qbase) * HEAD;
#pragma unroll
    for (int r = 0; r < 8; r++) {
        const float inv = 1.f / l_r[r];
        ob[(size_t)(rows0 + r) * HEAD + lane]      = acc[r][0] * inv;
        ob[(size_t)(rows0 + r) * HEAD + lane + 32] = acc[r][1] * inv;
    }
}

// ---------------------------------------------------------------------------
extern "C" void kernel_launch(void* const* d_in, const int* in_sizes, int n_in,
                              void* d_out, int out_size)
{
    (void)in_sizes; (void)n_in; (void)out_size;
    const float* emb = (const float*)d_in[0];
    const float* Wq  = (const float*)d_in[1];
    const float* Wk  = (const float*)d_in[2];
    const float* Wv  = (const float*)d_in[3];
    float* out = (float*)d_out;

    conv_e_kernel<<<(BATCH * SEQ * EMBED) / (256 * 4), 256>>>(emb);
    conv_w_kernel<<<(3 * HEAD * EMBED) / 256, 256>>>(Wq, Wk, Wv);

    cudaFuncSetAttribute(qkv_gemm_kernel, cudaFuncAttributeMaxDynamicSharedMemorySize,
                         2 * BUF_BYTES);
    qkv_gemm_kernel<<<(BATCH * SEQ) / 128, 512, 2 * BUF_BYTES>>>();

    const size_t smem = (64 * 64 + 2 * 64 * 68 + 64 * 64) * sizeof(float); // 67584 B
    cudaFuncSetAttribute(attn_kernel, cudaFuncAttributeMaxDynamicSharedMemorySize, (int)smem);
    attn_kernel<<<BATCH * (SEQ / BM), 256, smem>>>(out);
}

// round 4
// speedup vs baseline: 2.9258x; 2.5006x over previous
#include <cuda_runtime.h>
#include <cuda_bf16.h>
#include <cstdint>

#define BATCH 8
#define SEQ   2048
#define EMBED 1024
#define HEAD  64

// ---------------- device scratch ----------------
__device__ __nv_bfloat16 g_qhi[BATCH * SEQ * HEAD];
__device__ __nv_bfloat16 g_qlo[BATCH * SEQ * HEAD];
__device__ __nv_bfloat16 g_khi[BATCH * SEQ * HEAD];
__device__ __nv_bfloat16 g_klo[BATCH * SEQ * HEAD];
__device__ __nv_bfloat16 g_vhi[BATCH * SEQ * HEAD];
__device__ __nv_bfloat16 g_vlo[BATCH * SEQ * HEAD];

__device__ __nv_bfloat16 g_ehi[BATCH * SEQ * EMBED];
__device__ __nv_bfloat16 g_elo[BATCH * SEQ * EMBED];
__device__ __nv_bfloat16 g_bhi[3 * HEAD * EMBED];   // [192][1024], B[n][k] = W(k, n%64)
__device__ __nv_bfloat16 g_blo[3 * HEAD * EMBED];

#define NEG_INF __int_as_float(0xff800000)

__device__ __forceinline__ uint32_t smem_u32(const void* p) {
    uint32_t a;
    asm("{ .reg .u64 t; cvta.to.shared.u64 t, %1; cvt.u32.u64 %0, t; }" : "=r"(a) : "l"(p));
    return a;
}
__device__ __forceinline__ void cp16(uint32_t dst, const void* src) {
    asm volatile("cp.async.cg.shared.global [%0], [%1], 16;" :: "r"(dst), "l"(src) : "memory");
}
__device__ __forceinline__ void cp_commit() { asm volatile("cp.async.commit_group;" ::: "memory"); }
template <int N> __device__ __forceinline__ void cp_wait() {
    asm volatile("cp.async.wait_group %0;" :: "n"(N) : "memory");
}
__device__ __forceinline__ void ldm_x4(uint32_t (&r)[4], uint32_t addr) {
    asm volatile("ldmatrix.sync.aligned.m8n8.x4.shared.b16 {%0,%1,%2,%3}, [%4];"
                 : "=r"(r[0]), "=r"(r[1]), "=r"(r[2]), "=r"(r[3]) : "r"(addr));
}
__device__ __forceinline__ void ldm_x4_t(uint32_t (&r)[4], uint32_t addr) {
    asm volatile("ldmatrix.sync.aligned.m8n8.x4.trans.shared.b16 {%0,%1,%2,%3}, [%4];"
                 : "=r"(r[0]), "=r"(r[1]), "=r"(r[2]), "=r"(r[3]) : "r"(addr));
}
__device__ __forceinline__ void mma_bf16(float (&d)[4], const uint32_t (&a)[4],
                                         uint32_t b0, uint32_t b1) {
    asm volatile(
        "mma.sync.aligned.m16n8k16.row.col.f32.bf16.bf16.f32 "
        "{%0,%1,%2,%3}, {%4,%5,%6,%7}, {%8,%9}, {%0,%1,%2,%3};"
        : "+f"(d[0]), "+f"(d[1]), "+f"(d[2]), "+f"(d[3])
        : "r"(a[0]), "r"(a[1]), "r"(a[2]), "r"(a[3]), "r"(b0), "r"(b1));
}
__device__ __forceinline__ float ex2(float x) {
    float r; asm("ex2.approx.f32 %0, %1;" : "=f"(r) : "f"(x)); return r;
}

// ---------------------------------------------------------------------------
// Kernel 1: fp32 -> bf16 hi/lo split of embeddings
// ---------------------------------------------------------------------------
__global__ __launch_bounds__(256) void conv_e_kernel(const float* __restrict__ e)
{
    const size_t i = ((size_t)blockIdx.x * 256 + threadIdx.x) * 4;
    const float4 x = *(const float4*)(e + i);
    __nv_bfloat16 h0 = __float2bfloat16_rn(x.x), h1 = __float2bfloat16_rn(x.y);
    __nv_bfloat16 h2 = __float2bfloat16_rn(x.z), h3 = __float2bfloat16_rn(x.w);
    __nv_bfloat16 l0 = __float2bfloat16_rn(x.x - __bfloat162float(h0));
    __nv_bfloat16 l1 = __float2bfloat16_rn(x.y - __bfloat162float(h1));
    __nv_bfloat16 l2 = __float2bfloat16_rn(x.z - __bfloat162float(h2));
    __nv_bfloat16 l3 = __float2bfloat16_rn(x.w - __bfloat162float(h3));
    __nv_bfloat162* hp = (__nv_bfloat162*)(g_ehi + i);
    __nv_bfloat162* lp = (__nv_bfloat162*)(g_elo + i);
    hp[0] = __halves2bfloat162(h0, h1);
    hp[1] = __halves2bfloat162(h2, h3);
    lp[0] = __halves2bfloat162(l0, l1);
    lp[1] = __halves2bfloat162(l2, l3);
}

// ---------------------------------------------------------------------------
// Kernel 2: build B[n][k] = W(k, n%64), n in [0,192), hi/lo bf16 split
// ---------------------------------------------------------------------------
__global__ __launch_bounds__(256) void conv_w_kernel(
    const float* __restrict__ Wq, const float* __restrict__ Wk, const float* __restrict__ Wv)
{
    const int idx = blockIdx.x * 256 + threadIdx.x;   // 192*1024 total
    const int n = idx >> 10, k = idx & 1023;
    const float* W = (n < 64) ? Wq : ((n < 128) ? Wk : Wv);
    const float x = W[k * HEAD + (n & 63)];
    const __nv_bfloat16 h = __float2bfloat16_rn(x);
    g_bhi[idx] = h;
    g_blo[idx] = __float2bfloat16_rn(x - __bfloat162float(h));
}

// ---------------------------------------------------------------------------
// Kernel 3: fused QKV projection via mma.sync (bf16, fp32 accum, 3-term hi/lo).
// Epilogue emits Q,K,V as bf16 hi/lo pairs; Q pre-scaled by 0.125*log2(e).
// ---------------------------------------------------------------------------
#define KCH   64
#define A_BYTES (128 * 72 * 2)          // pitch 144 B
#define B_BYTES (192 * 72 * 2)
#define BUF_BYTES (A_BYTES + B_BYTES)   // 46080

#define QSCALE 0.18033688f              // 0.125 * log2(e)

__global__ __launch_bounds__(512) void qkv_gemm_kernel()
{
    extern __shared__ char smg[];
    const int tid  = threadIdx.x;
    const int wid  = tid >> 5, lane = tid & 31;
    const int wm   = wid >> 2, wn = wid & 3;      // 4x4 warp grid
    const size_t row0 = (size_t)blockIdx.x * 128;

    const uint32_t smb = smem_u32(smg);

    float acc[2][6][4];
#pragma unroll
    for (int mi = 0; mi < 2; mi++)
#pragma unroll
        for (int nj = 0; nj < 6; nj++)
#pragma unroll
            for (int f = 0; f < 4; f++) acc[mi][nj][f] = 0.f;

    auto issue = [&](int c, int buf) {
        const int p  = c >> 4;
        const int k0 = (c & 15) * KCH;
        const __nv_bfloat16* As = (p == 1) ? g_elo : g_ehi;
        const __nv_bfloat16* Bs = (p == 2) ? g_blo : g_bhi;
        const uint32_t aBase = smb + buf * BUF_BYTES;
        const uint32_t bBase = aBase + A_BYTES;
#pragma unroll
        for (int j = 0; j < 2; j++) {
            const int idx = tid + 512 * j;
            const int r = idx >> 3, v = idx & 7;
            cp16(aBase + r * 144 + v * 16, As + (row0 + r) * (size_t)EMBED + k0 + v * 8);
        }
#pragma unroll
        for (int j = 0; j < 3; j++) {
            const int idx = tid + 512 * j;
            const int n = idx >> 3, v = idx & 7;
            cp16(bBase + n * 144 + v * 16, Bs + n * (size_t)EMBED + k0 + v * 8);
        }
        cp_commit();
    };

    issue(0, 0);

    for (int c = 0; c < 48; c++) {
        if (c < 47) {
            issue(c + 1, (c + 1) & 1);
            cp_wait<1>();
        } else {
            cp_wait<0>();
        }
        __syncthreads();

        const uint32_t aBase = smb + (c & 1) * BUF_BYTES;
        const uint32_t bBase = aBase + A_BYTES;

#pragma unroll
        for (int ks = 0; ks < 4; ks++) {
            uint32_t a[2][4];
#pragma unroll
            for (int mi = 0; mi < 2; mi++) {
                const int row = wm * 32 + mi * 16 + (lane & 15);
                ldm_x4(a[mi], aBase + (uint32_t)(row * 144 + ks * 32 + (lane >> 4) * 16));
            }
            uint32_t bt[3][4];
#pragma unroll
            for (int nb = 0; nb < 3; nb++) {
                const int nrow = wn * 48 + nb * 16 + (lane & 7) + ((lane >> 4) << 3);
                const int koff = (lane >> 3) & 1;
                ldm_x4(bt[nb], bBase + (uint32_t)(nrow * 144 + ks * 32 + koff * 16));
            }
#pragma unroll
            for (int mi = 0; mi < 2; mi++)
#pragma unroll
                for (int nj = 0; nj < 6; nj++)
                    mma_bf16(acc[mi][nj], a[mi], bt[nj >> 1][(nj & 1) * 2],
                             bt[nj >> 1][(nj & 1) * 2 + 1]);
        }
        __syncthreads();
    }

    // Epilogue: hi/lo bf16 split straight to g_{q,k,v}{hi,lo}
    const int g = lane >> 2, t = lane & 3;
#pragma unroll
    for (int mi = 0; mi < 2; mi++) {
#pragma unroll
        for (int nj = 0; nj < 6; nj++) {
            const int colg = wn * 48 + nj * 8;
            const int grp  = colg >> 6;
            const int nc   = (colg & 63) + 2 * t;
            __nv_bfloat16* dh = (grp == 0) ? g_qhi : ((grp == 1) ? g_khi : g_vhi);
            __nv_bfloat16* dl = (grp == 0) ? g_qlo : ((grp == 1) ? g_klo : g_vlo);
            const float s = (grp == 0) ? QSCALE : 1.0f;
            const size_t r = row0 + wm * 32 + mi * 16 + g;

            float x = acc[mi][nj][0] * s, y = acc[mi][nj][1] * s;
            __nv_bfloat16 hx = __float2bfloat16_rn(x), hy = __float2bfloat16_rn(y);
            *(__nv_bfloat162*)&dh[r * HEAD + nc] = __halves2bfloat162(hx, hy);
            *(__nv_bfloat162*)&dl[r * HEAD + nc] =
                __floats2bfloat162_rn(x - __bfloat162float(hx), y - __bfloat162float(hy));

            x = acc[mi][nj][2] * s; y = acc[mi][nj][3] * s;
            hx = __float2bfloat16_rn(x); hy = __float2bfloat16_rn(y);
            *(__nv_bfloat162*)&dh[(r + 8) * HEAD + nc] = __halves2bfloat162(hx, hy);
            *(__nv_bfloat162*)&dl[(r + 8) * HEAD + nc] =
                __floats2bfloat162_rn(x - __bfloat162float(hx), y - __bfloat162float(hy));
        }
    }
}

// ---------------------------------------------------------------------------
// Kernel 4: causal flash attention on mma.sync bf16 (3-term compensated).
// CTA = 64 queries, 128 threads (4 warps x 16 rows). BN = 64 keys/tile.
// ---------------------------------------------------------------------------
#define AT_TBYTES (64 * 144)            // one 64x64 bf16 tile, pitch 144B
#define OFF_KHI 0
#define OFF_KLO (AT_TBYTES)
#define OFF_VHI (2 * AT_TBYTES)
#define OFF_VLO (3 * AT_TBYTES)
#define AT_BUF  (4 * AT_TBYTES)         // 36864 per buffer

__global__ __launch_bounds__(128, 2) void attn_kernel(float* __restrict__ out)
{
    extern __shared__ char sma[];
    const uint32_t smb = smem_u32(sma);
    const int tid = threadIdx.x, lane = tid & 31, w = tid >> 5;

    // balanced causal schedule: co-resident pair (bid, bid+148) gets
    // complementary weights (sorted-desc index s; weight = 32 - s/8).
    const int s  = (blockIdx.x < 148) ? blockIdx.x : (403 - blockIdx.x);
    const int qt = 31 - (s >> 3);
    const int b  = s & 7;
    const int qbase = qt * 64;

    const __nv_bfloat16* qhig = g_qhi + ((size_t)b * SEQ + qbase) * HEAD;
    const __nv_bfloat16* qlog = g_qlo + ((size_t)b * SEQ + qbase) * HEAD;
    const __nv_bfloat16* khig = g_khi + (size_t)b * SEQ * HEAD;
    const __nv_bfloat16* klog = g_klo + (size_t)b * SEQ * HEAD;
    const __nv_bfloat16* vhig = g_vhi + (size_t)b * SEQ * HEAD;
    const __nv_bfloat16* vlog = g_vlo + (size_t)b * SEQ * HEAD;

    // ---- stage Q in buf0, load A-fragments once ----
#pragma unroll
    for (int j = 0; j < 4; j++) {
        const int idx = tid + 128 * j;
        const int r = idx >> 3, c = idx & 7;
        *(float4*)(sma + OFF_KHI + r * 144 + c * 16) = *(const float4*)(qhig + r * HEAD + c * 8);
        *(float4*)(sma + OFF_KLO + r * 144 + c * 16) = *(const float4*)(qlog + r * HEAD + c * 8);
    }
    __syncthreads();
    uint32_t ahi[4][4], alo[4][4];
    {
        const int row  = w * 16 + (lane & 7) + (((lane >> 3) & 1) << 3);
        const uint32_t colb = (lane >> 4) << 4;
#pragma unroll
        for (int c = 0; c < 4; c++) {
            ldm_x4(ahi[c], smb + OFF_KHI + row * 144 + c * 32 + colb);
            ldm_x4(alo[c], smb + OFF_KLO + row * 144 + c * 32 + colb);
        }
    }
    __syncthreads();

    auto issueTile = [&](int kt, int buf) {
        const uint32_t base = smb + buf * AT_BUF;
        const size_t ko = (size_t)kt * 64 * HEAD;
#pragma unroll
        for (int j = 0; j < 4; j++) {
            const int idx = tid + 128 * j;
            const int r = idx >> 3, c = idx & 7;
            const uint32_t so = (uint32_t)(r * 144 + c * 16);
            const size_t go = ko + (size_t)r * HEAD + c * 8;
            cp16(base + OFF_KHI + so, khig + go);
            cp16(base + OFF_KLO + so, klog + go);
            cp16(base + OFF_VHI + so, vhig + go);
            cp16(base + OFF_VLO + so, vlog + go);
        }
        cp_commit();
    };

    issueTile(0, 0);

    float m0 = NEG_INF, m1 = NEG_INF, l0 = 0.f, l1 = 0.f;
    float of[8][4];
#pragma unroll
    for (int j = 0; j < 8; j++)
#pragma unroll
        for (int f = 0; f < 4; f++) of[j][f] = 0.f;

    for (int kt = 0; kt <= qt; kt++) {
        if (kt < qt) { issueTile(kt + 1, (kt + 1) & 1); cp_wait<1>(); }
        else         { cp_wait<0>(); }
        __syncthreads();
        const uint32_t base = smb + (kt & 1) * AT_BUF;

        // ---- S = Q K^T (3 compensated terms) ----
        float sf[8][4];
#pragma unroll
        for (int j = 0; j < 8; j++)
#pragma unroll
            for (int f = 0; f < 4; f++) sf[j][f] = 0.f;

        {
            const int key = (lane & 7) + ((lane >> 4) << 3);
            const uint32_t colb = ((lane >> 3) & 1) << 4;
#pragma unroll
            for (int c = 0; c < 4; c++) {
                uint32_t kh[4][4], kl[4][4];
#pragma unroll
                for (int g = 0; g < 4; g++) {
                    const uint32_t a = base + (uint32_t)((g * 16 + key) * 144 + c * 32) + colb;
                    ldm_x4(kh[g], a + OFF_KHI);
                    ldm_x4(kl[g], a + OFF_KLO);
                }
#pragma unroll
                for (int g = 0; g < 4; g++) {
                    mma_bf16(sf[2 * g],     ahi[c], kh[g][0], kh[g][1]);
                    mma_bf16(sf[2 * g],     alo[c], kh[g][0], kh[g][1]);
                    mma_bf16(sf[2 * g],     ahi[c], kl[g][0], kl[g][1]);
                    mma_bf16(sf[2 * g + 1], ahi[c], kh[g][2], kh[g][3]);
                    mma_bf16(sf[2 * g + 1], alo[c], kh[g][2], kh[g][3]);
                    mma_bf16(sf[2 * g + 1], ahi[c], kl[g][2], kl[g][3]);
                }
            }
        }

        // ---- causal mask on diagonal tile ----
        if (kt == qt) {
            const int qg0 = qbase + w * 16 + (lane >> 2);
            const int kb0 = kt * 64 + 2 * (lane & 3);
#pragma unroll
            for (int j = 0; j < 8; j++) {
                const int k0g = kb0 + 8 * j;
                if (k0g     > qg0)     sf[j][0] = NEG_INF;
                if (k0g + 1 > qg0)     sf[j][1] = NEG_INF;
                if (k0g     > qg0 + 8) sf[j][2] = NEG_INF;
                if (k0g + 1 > qg0 + 8) sf[j][3] = NEG_INF;
            }
        }

        // ---- online softmax (log2 domain; scale folded into Q) ----
        float mx0 = NEG_INF, mx1 = NEG_INF;
#pragma unroll
        for (int j = 0; j < 8; j++) {
            mx0 = fmaxf(mx0, fmaxf(sf[j][0], sf[j][1]));
            mx1 = fmaxf(mx1, fmaxf(sf[j][2], sf[j][3]));
        }
        mx0 = fmaxf(mx0, __shfl_xor_sync(0xffffffffu, mx0, 1));
        mx0 = fmaxf(mx0, __shfl_xor_sync(0xffffffffu, mx0, 2));
        mx1 = fmaxf(mx1, __shfl_xor_sync(0xffffffffu, mx1, 1));
        mx1 = fmaxf(mx1, __shfl_xor_sync(0xffffffffu, mx1, 2));
        const float mn0 = fmaxf(m0, mx0), mn1 = fmaxf(m1, mx1);
        const float cr0 = ex2(m0 - mn0), cr1 = ex2(m1 - mn1);
        m0 = mn0; m1 = mn1;
        float rs0 = 0.f, rs1 = 0.f;
#pragma unroll
        for (int j = 0; j < 8; j++) {
            sf[j][0] = ex2(sf[j][0] - mn0); rs0 += sf[j][0];
            sf[j][1] = ex2(sf[j][1] - mn0); rs0 += sf[j][1];
            sf[j][2] = ex2(sf[j][2] - mn1); rs1 += sf[j][2];
            sf[j][3] = ex2(sf[j][3] - mn1); rs1 += sf[j][3];
        }
        rs0 += __shfl_xor_sync(0xffffffffu, rs0, 1);
        rs0 += __shfl_xor_sync(0xffffffffu, rs0, 2);
        rs1 += __shfl_xor_sync(0xffffffffu, rs1, 1);
        rs1 += __shfl_xor_sync(0xffffffffu, rs1, 2);
        l0 = l0 * cr0 + rs0;
        l1 = l1 * cr1 + rs1;
#pragma unroll
        for (int j = 0; j < 8; j++) {
            of[j][0] *= cr0; of[j][1] *= cr0;
            of[j][2] *= cr1; of[j][3] *= cr1;
        }

        // ---- pack P to bf16 hi/lo A-fragments (register-only remap) ----
        uint32_t ph[4][4], pl[4][4];
#pragma unroll
        for (int t = 0; t < 4; t++) {
#pragma unroll
            for (int q = 0; q < 4; q++) {
                const int j = 2 * t + (q >> 1);
                const int e = (q & 1) * 2;
                const float x = sf[j][e], y = sf[j][e + 1];
                const __nv_bfloat16 hx = __float2bfloat16_rn(x), hy = __float2bfloat16_rn(y);
                const __nv_bfloat162 hp = __halves2bfloat162(hx, hy);
                ph[t][q] = *(const uint32_t*)&hp;
                const __nv_bfloat162 lp = __floats2bfloat162_rn(
                    x - __bfloat162float(hx), y - __bfloat162float(hy));
                pl[t][q] = *(const uint32_t*)&lp;
            }
        }

        // ---- O += P V (3 compensated terms) ----
        {
            const uint32_t colb = (lane >> 4) << 4;
#pragma unroll
            for (int t = 0; t < 4; t++) {
                uint32_t vh[4][4], vl[4][4];
                const int key = 16 * t + (lane & 7) + (((lane >> 3) & 1) << 3);
#pragma unroll
                for (int h = 0; h < 4; h++) {
                    const uint32_t a = base + (uint32_t)(key * 144 + h * 32) + colb;
                    ldm_x4_t(vh[h], a + OFF_VHI);
                    ldm_x4_t(vl[h], a + OFF_VLO);
                }
#pragma unroll
                for (int h = 0; h < 4; h++) {
                    mma_bf16(of[2 * h],     ph[t], vh[h][0], vh[h][1]);
                    mma_bf16(of[2 * h],     pl[t], vh[h][0], vh[h][1]);
                    mma_bf16(of[2 * h],     ph[t], vl[h][0], vl[h][1]);
                    mma_bf16(of[2 * h + 1], ph[t], vh[h][2], vh[h][3]);
                    mma_bf16(of[2 * h + 1], pl[t], vh[h][2], vh[h][3]);
                    mma_bf16(of[2 * h + 1], ph[t], vl[h][2], vl[h][3]);
                }
            }
        }
        __syncthreads();   // compute done before next prefetch overwrites this buffer
    }

    // ---- normalize + store ----
    const float inv0 = 1.f / l0, inv1 = 1.f / l1;
    float* ob = out + ((size_t)b * SEQ + qbase + w * 16) * HEAD;
    const int r0 = lane >> 2, cb = 2 * (lane & 3);
#pragma unroll
    for (int j = 0; j < 8; j++) {
        *(float2*)&ob[(size_t)r0 * HEAD + 8 * j + cb] =
            make_float2(of[j][0] * inv0, of[j][1] * inv0);
        *(float2*)&ob[(size_t)(r0 + 8) * HEAD + 8 * j + cb] =
            make_float2(of[j][2] * inv1, of[j][3] * inv1);
    }
}

// ---------------------------------------------------------------------------
extern "C" void kernel_launch(void* const* d_in, const int* in_sizes, int n_in,
                              void* d_out, int out_size)
{
    (void)in_sizes; (void)n_in; (void)out_size;
    const float* emb = (const float*)d_in[0];
    const float* Wq  = (const float*)d_in[1];
    const float* Wk  = (const float*)d_in[2];
    const float* Wv  = (const float*)d_in[3];
    float* out = (float*)d_out;

    conv_e_kernel<<<(BATCH * SEQ * EMBED) / (256 * 4), 256>>>(emb);
    conv_w_kernel<<<(3 * HEAD * EMBED) / 256, 256>>>(Wq, Wk, Wv);

    cudaFuncSetAttribute(qkv_gemm_kernel, cudaFuncAttributeMaxDynamicSharedMemorySize,
                         2 * BUF_BYTES);
    qkv_gemm_kernel<<<(BATCH * SEQ) / 128, 512, 2 * BUF_BYTES>>>();

    cudaFuncSetAttribute(attn_kernel, cudaFuncAttributeMaxDynamicSharedMemorySize,
                         2 * AT_BUF);
    attn_kernel<<<256, 128, 2 * AT_BUF>>>(out);
}

// round 5
// speedup vs baseline: 3.4789x; 1.1891x over previous
#include <cuda_runtime.h>
#include <cuda_bf16.h>
#include <cstdint>

#define BATCH 8
#define SEQ   2048
#define EMBED 1024
#define HEAD  64

// ---------------- device scratch ----------------
__device__ __nv_bfloat16 g_qhi[BATCH * SEQ * HEAD];
__device__ __nv_bfloat16 g_qlo[BATCH * SEQ * HEAD];
__device__ __nv_bfloat16 g_khi[BATCH * SEQ * HEAD];
__device__ __nv_bfloat16 g_klo[BATCH * SEQ * HEAD];
__device__ __nv_bfloat16 g_vhi[BATCH * SEQ * HEAD];
__device__ __nv_bfloat16 g_vlo[BATCH * SEQ * HEAD];

__device__ __nv_bfloat16 g_bhi[3 * HEAD * EMBED];   // [192][1024], B[n][k] = W(k, n%64)
__device__ __nv_bfloat16 g_blo[3 * HEAD * EMBED];

#define NEG_INF __int_as_float(0xff800000)
#define QSCALE 0.18033688f              // 0.125 * log2(e)

__device__ __forceinline__ uint32_t smem_u32(const void* p) {
    uint32_t a;
    asm("{ .reg .u64 t; cvta.to.shared.u64 t, %1; cvt.u32.u64 %0, t; }" : "=r"(a) : "l"(p));
    return a;
}
__device__ __forceinline__ void cp16(uint32_t dst, const void* src) {
    asm volatile("cp.async.cg.shared.global [%0], [%1], 16;" :: "r"(dst), "l"(src) : "memory");
}
__device__ __forceinline__ void cp_commit() { asm volatile("cp.async.commit_group;" ::: "memory"); }
template <int N> __device__ __forceinline__ void cp_wait() {
    asm volatile("cp.async.wait_group %0;" :: "n"(N) : "memory");
}
__device__ __forceinline__ void ldm_x4(uint32_t (&r)[4], uint32_t addr) {
    asm volatile("ldmatrix.sync.aligned.m8n8.x4.shared.b16 {%0,%1,%2,%3}, [%4];"
                 : "=r"(r[0]), "=r"(r[1]), "=r"(r[2]), "=r"(r[3]) : "r"(addr));
}
__device__ __forceinline__ void ldm_x4_t(uint32_t (&r)[4], uint32_t addr) {
    asm volatile("ldmatrix.sync.aligned.m8n8.x4.trans.shared.b16 {%0,%1,%2,%3}, [%4];"
                 : "=r"(r[0]), "=r"(r[1]), "=r"(r[2]), "=r"(r[3]) : "r"(addr));
}
__device__ __forceinline__ void mma_bf16(float (&d)[4], const uint32_t (&a)[4],
                                         uint32_t b0, uint32_t b1) {
    asm volatile(
        "mma.sync.aligned.m16n8k16.row.col.f32.bf16.bf16.f32 "
        "{%0,%1,%2,%3}, {%4,%5,%6,%7}, {%8,%9}, {%0,%1,%2,%3};"
        : "+f"(d[0]), "+f"(d[1]), "+f"(d[2]), "+f"(d[3])
        : "r"(a[0]), "r"(a[1]), "r"(a[2]), "r"(a[3]), "r"(b0), "r"(b1));
}
__device__ __forceinline__ float ex2(float x) {
    float r; asm("ex2.approx.f32 %0, %1;" : "=f"(r) : "f"(x)); return r;
}
__device__ __forceinline__ uint32_t pack_hi(float x, float y, uint32_t& lo) {
    const __nv_bfloat16 hx = __float2bfloat16_rn(x), hy = __float2bfloat16_rn(y);
    const __nv_bfloat162 hp = __halves2bfloat162(hx, hy);
    const __nv_bfloat162 lp = __floats2bfloat162_rn(x - __bfloat162float(hx),
                                                    y - __bfloat162float(hy));
    lo = *(const uint32_t*)&lp;
    return *(const uint32_t*)&hp;
}

// ---------------------------------------------------------------------------
// Kernel 1: build B[n][k] = W(k, n%64), n in [0,192), hi/lo bf16 split
// ---------------------------------------------------------------------------
__global__ __launch_bounds__(256) void conv_w_kernel(
    const float* __restrict__ Wq, const float* __restrict__ Wk, const float* __restrict__ Wv)
{
    const int idx = blockIdx.x * 256 + threadIdx.x;   // 192*1024 total
    const int n = idx >> 10, k = idx & 1023;
    const float* W = (n < 64) ? Wq : ((n < 128) ? Wk : Wv);
    const float x = W[k * HEAD + (n & 63)];
    const __nv_bfloat16 h = __float2bfloat16_rn(x);
    g_bhi[idx] = h;
    g_blo[idx] = __float2bfloat16_rn(x - __bfloat162float(h));
}

// ---------------------------------------------------------------------------
// Kernel 2: fused QKV projection. A (fp32) loaded via register prefetch,
// split to bf16 hi/lo in-kernel; B hi/lo staged via cp.async. All 3
// compensation terms (Ahi*Bhi + Alo*Bhi + Ahi*Blo) per K-chunk of 64.
// CTA: 128 rows x 192 cols, 256 threads = 8 warps (2m x 4n), warp 64x48.
// ---------------------------------------------------------------------------
#define EHI_OFF(buf) ((buf) * 36864)
#define ELO_OFF(buf) ((buf) * 36864 + 18432)
#define BHI_OFF(buf) (73728 + (buf) * 55296)
#define BLO_OFF(buf) (73728 + (buf) * 55296 + 27648)
#define GEMM_SMEM 184320

__global__ __launch_bounds__(256) void qkv_gemm_kernel(const float* __restrict__ emb)
{
    extern __shared__ char smg[];
    const uint32_t smb = smem_u32(smg);
    const int tid  = threadIdx.x;
    const int wid  = tid >> 5, lane = tid & 31;
    const int wm   = wid >> 2, wn = wid & 3;      // 2x4 warp grid
    const size_t row0 = (size_t)blockIdx.x * 128;

    float acc[4][6][4];
#pragma unroll
    for (int mi = 0; mi < 4; mi++)
#pragma unroll
        for (int nj = 0; nj < 6; nj++)
#pragma unroll
            for (int f = 0; f < 4; f++) acc[mi][nj][f] = 0.f;

    // A prefetch: thread owns rows (r, r+64), 16 consecutive floats each
    const int ar = tid >> 2;
    const int ac = (tid & 3) * 16;
    float4 pa[8];

    auto loadA = [&](int c) {
        const int k0 = c * 64;
        const float* p0 = emb + (row0 + ar) * (size_t)EMBED + k0 + ac;
        const float* p1 = emb + (row0 + ar + 64) * (size_t)EMBED + k0 + ac;
#pragma unroll
        for (int j = 0; j < 4; j++) {
            pa[j]     = *(const float4*)(p0 + 4 * j);
            pa[4 + j] = *(const float4*)(p1 + 4 * j);
        }
    };
    auto stageA = [&](int buf) {
#pragma unroll
        for (int j = 0; j < 8; j++) {
            const int row = ar + (j >> 2) * 64;
            const int c0  = ac + (j & 3) * 4;
            uint32_t lo0, lo1;
            const uint32_t h0 = pack_hi(pa[j].x, pa[j].y, lo0);
            const uint32_t h1 = pack_hi(pa[j].z, pa[j].w, lo1);
            const int off = row * 144 + c0 * 2;
            *(uint2*)(smg + EHI_OFF(buf) + off) = make_uint2(h0, h1);
            *(uint2*)(smg + ELO_OFF(buf) + off) = make_uint2(lo0, lo1);
        }
    };
    auto issueB = [&](int c, int buf) {
        const int k0 = c * 64;
#pragma unroll
        for (int j = 0; j < 6; j++) {
            const int i = tid + 256 * j;
            const int n = i >> 3, v = i & 7;
            const uint32_t so = (uint32_t)(n * 144 + v * 16);
            const size_t go = (size_t)n * EMBED + k0 + v * 8;
            cp16(smb + BHI_OFF(buf) + so, g_bhi + go);
            cp16(smb + BLO_OFF(buf) + so, g_blo + go);
        }
        cp_commit();
    };

    loadA(0);
    issueB(0, 0);

    for (int c = 0; c < 16; c++) {
        const int buf = c & 1;
        stageA(buf);
        if (c < 15) {
            loadA(c + 1);            // regs free after stageA
            issueB(c + 1, buf ^ 1);
            cp_wait<1>();
        } else {
            cp_wait<0>();
        }
        __syncthreads();

#pragma unroll
        for (int ks = 0; ks < 4; ks++) {
            uint32_t ahi[4][4], alo[4][4];
#pragma unroll
            for (int mi = 0; mi < 4; mi++) {
                const uint32_t ro = (uint32_t)((wm * 64 + mi * 16 + (lane & 15)) * 144
                                               + ks * 32 + (lane >> 4) * 16);
                ldm_x4(ahi[mi], smb + EHI_OFF(buf) + ro);
                ldm_x4(alo[mi], smb + ELO_OFF(buf) + ro);
            }
            uint32_t bhi[3][4], blo[3][4];
#pragma unroll
            for (int nb = 0; nb < 3; nb++) {
                const uint32_t ro = (uint32_t)((wn * 48 + nb * 16 + (lane & 7)
                                                + ((lane >> 4) << 3)) * 144
                                               + ks * 32 + (((lane >> 3) & 1) << 4));
                ldm_x4(bhi[nb], smb + BHI_OFF(buf) + ro);
                ldm_x4(blo[nb], smb + BLO_OFF(buf) + ro);
            }
#pragma unroll
            for (int mi = 0; mi < 4; mi++)
#pragma unroll
                for (int nj = 0; nj < 6; nj++) {
                    const uint32_t b0h = bhi[nj >> 1][(nj & 1) * 2];
                    const uint32_t b1h = bhi[nj >> 1][(nj & 1) * 2 + 1];
                    mma_bf16(acc[mi][nj], ahi[mi], b0h, b1h);
                    mma_bf16(acc[mi][nj], alo[mi], b0h, b1h);
                    mma_bf16(acc[mi][nj], ahi[mi], blo[nj >> 1][(nj & 1) * 2],
                             blo[nj >> 1][(nj & 1) * 2 + 1]);
                }
        }
        __syncthreads();
    }

    // Epilogue: hi/lo bf16 split straight to g_{q,k,v}{hi,lo}
    const int g = lane >> 2, t = lane & 3;
#pragma unroll
    for (int mi = 0; mi < 4; mi++) {
#pragma unroll
        for (int nj = 0; nj < 6; nj++) {
            const int colg = wn * 48 + nj * 8;
            const int grp  = colg >> 6;
            const int nc   = (colg & 63) + 2 * t;
            __nv_bfloat16* dh = (grp == 0) ? g_qhi : ((grp == 1) ? g_khi : g_vhi);
            __nv_bfloat16* dl = (grp == 0) ? g_qlo : ((grp == 1) ? g_klo : g_vlo);
            const float s = (grp == 0) ? QSCALE : 1.0f;
            const size_t r = row0 + wm * 64 + mi * 16 + g;

            uint32_t lo;
            uint32_t hi = pack_hi(acc[mi][nj][0] * s, acc[mi][nj][1] * s, lo);
            *(uint32_t*)&dh[r * HEAD + nc] = hi;
            *(uint32_t*)&dl[r * HEAD + nc] = lo;
            hi = pack_hi(acc[mi][nj][2] * s, acc[mi][nj][3] * s, lo);
            *(uint32_t*)&dh[(r + 8) * HEAD + nc] = hi;
            *(uint32_t*)&dl[(r + 8) * HEAD + nc] = lo;
        }
    }
}

// ---------------------------------------------------------------------------
// Kernel 3: causal flash attention on mma.sync bf16 (3-term compensated,
// split hi/lo accumulation chains). CTA = 64 queries, 128 threads.
// ---------------------------------------------------------------------------
#define AT_TBYTES (64 * 144)
#define OFF_KHI 0
#define OFF_KLO (AT_TBYTES)
#define OFF_VHI (2 * AT_TBYTES)
#define OFF_VLO (3 * AT_TBYTES)
#define AT_BUF  (4 * AT_TBYTES)         // 36864 per buffer

__global__ __launch_bounds__(128, 2) void attn_kernel(float* __restrict__ out)
{
    extern __shared__ char sma[];
    const uint32_t smb = smem_u32(sma);
    const int tid = threadIdx.x, lane = tid & 31, w = tid >> 5;

    // balanced causal schedule: co-resident pair (bid, bid+148) complementary
    const int s  = (blockIdx.x < 148) ? blockIdx.x : (403 - blockIdx.x);
    const int qt = 31 - (s >> 3);
    const int b  = s & 7;
    const int qbase = qt * 64;

    const __nv_bfloat16* qhig = g_qhi + ((size_t)b * SEQ + qbase) * HEAD;
    const __nv_bfloat16* qlog = g_qlo + ((size_t)b * SEQ + qbase) * HEAD;
    const __nv_bfloat16* khig = g_khi + (size_t)b * SEQ * HEAD;
    const __nv_bfloat16* klog = g_klo + (size_t)b * SEQ * HEAD;
    const __nv_bfloat16* vhig = g_vhi + (size_t)b * SEQ * HEAD;
    const __nv_bfloat16* vlog = g_vlo + (size_t)b * SEQ * HEAD;

    // ---- stage Q in buf0, load A-fragments once ----
#pragma unroll
    for (int j = 0; j < 4; j++) {
        const int idx = tid + 128 * j;
        const int r = idx >> 3, c = idx & 7;
        *(float4*)(sma + OFF_KHI + r * 144 + c * 16) = *(const float4*)(qhig + r * HEAD + c * 8);
        *(float4*)(sma + OFF_KLO + r * 144 + c * 16) = *(const float4*)(qlog + r * HEAD + c * 8);
    }
    __syncthreads();
    uint32_t ahi[4][4], alo[4][4];
    {
        const int row  = w * 16 + (lane & 7) + (((lane >> 3) & 1) << 3);
        const uint32_t colb = (lane >> 4) << 4;
#pragma unroll
        for (int c = 0; c < 4; c++) {
            ldm_x4(ahi[c], smb + OFF_KHI + row * 144 + c * 32 + colb);
            ldm_x4(alo[c], smb + OFF_KLO + row * 144 + c * 32 + colb);
        }
    }
    __syncthreads();

    auto issueTile = [&](int kt, int buf) {
        const uint32_t base = smb + buf * AT_BUF;
        const size_t ko = (size_t)kt * 64 * HEAD;
#pragma unroll
        for (int j = 0; j < 4; j++) {
            const int idx = tid + 128 * j;
            const int r = idx >> 3, c = idx & 7;
            const uint32_t so = (uint32_t)(r * 144 + c * 16);
            const size_t go = ko + (size_t)r * HEAD + c * 8;
            cp16(base + OFF_KHI + so, khig + go);
            cp16(base + OFF_KLO + so, klog + go);
            cp16(base + OFF_VHI + so, vhig + go);
            cp16(base + OFF_VLO + so, vlog + go);
        }
        cp_commit();
    };

    issueTile(0, 0);

    float m0 = NEG_INF, m1 = NEG_INF, l0 = 0.f, l1 = 0.f;
    float of[8][4];
#pragma unroll
    for (int j = 0; j < 8; j++)
#pragma unroll
        for (int f = 0; f < 4; f++) of[j][f] = 0.f;

    for (int kt = 0; kt <= qt; kt++) {
        if (kt < qt) { issueTile(kt + 1, (kt + 1) & 1); cp_wait<1>(); }
        else         { cp_wait<0>(); }
        __syncthreads();
        const uint32_t base = smb + (kt & 1) * AT_BUF;

        // ---- S = Q K^T; hi term -> sf, lo terms -> sfl (independent chains)
        float sf[8][4], sfl[8][4];
#pragma unroll
        for (int j = 0; j < 8; j++)
#pragma unroll
            for (int f = 0; f < 4; f++) { sf[j][f] = 0.f; sfl[j][f] = 0.f; }

        {
            const int key = (lane & 7) + ((lane >> 4) << 3);
            const uint32_t colb = ((lane >> 3) & 1) << 4;
#pragma unroll
            for (int c = 0; c < 4; c++) {
                uint32_t kh[4][4], kl[4][4];
#pragma unroll
                for (int g = 0; g < 4; g++) {
                    const uint32_t a = base + (uint32_t)((g * 16 + key) * 144 + c * 32) + colb;
                    ldm_x4(kh[g], a + OFF_KHI);
                    ldm_x4(kl[g], a + OFF_KLO);
                }
#pragma unroll
                for (int g = 0; g < 4; g++) {
                    mma_bf16(sf[2 * g],      ahi[c], kh[g][0], kh[g][1]);
                    mma_bf16(sfl[2 * g],     alo[c], kh[g][0], kh[g][1]);
                    mma_bf16(sfl[2 * g],     ahi[c], kl[g][0], kl[g][1]);
                    mma_bf16(sf[2 * g + 1],  ahi[c], kh[g][2], kh[g][3]);
                    mma_bf16(sfl[2 * g + 1], alo[c], kh[g][2], kh[g][3]);
                    mma_bf16(sfl[2 * g + 1], ahi[c], kl[g][2], kl[g][3]);
                }
            }
        }
#pragma unroll
        for (int j = 0; j < 8; j++)
#pragma unroll
            for (int f = 0; f < 4; f++) sf[j][f] += sfl[j][f];

        // ---- causal mask on diagonal tile ----
        if (kt == qt) {
            const int qg0 = qbase + w * 16 + (lane >> 2);
            const int kb0 = kt * 64 + 2 * (lane & 3);
#pragma unroll
            for (int j = 0; j < 8; j++) {
                const int k0g = kb0 + 8 * j;
                if (k0g     > qg0)     sf[j][0] = NEG_INF;
                if (k0g + 1 > qg0)     sf[j][1] = NEG_INF;
                if (k0g     > qg0 + 8) sf[j][2] = NEG_INF;
                if (k0g + 1 > qg0 + 8) sf[j][3] = NEG_INF;
            }
        }

        // ---- online softmax (log2 domain; scale folded into Q) ----
        float mx0 = NEG_INF, mx1 = NEG_INF;
#pragma unroll
        for (int j = 0; j < 8; j++) {
            mx0 = fmaxf(mx0, fmaxf(sf[j][0], sf[j][1]));
            mx1 = fmaxf(mx1, fmaxf(sf[j][2], sf[j][3]));
        }
        mx0 = fmaxf(mx0, __shfl_xor_sync(0xffffffffu, mx0, 1));
        mx0 = fmaxf(mx0, __shfl_xor_sync(0xffffffffu, mx0, 2));
        mx1 = fmaxf(mx1, __shfl_xor_sync(0xffffffffu, mx1, 1));
        mx1 = fmaxf(mx1, __shfl_xor_sync(0xffffffffu, mx1, 2));
        const float mn0 = fmaxf(m0, mx0), mn1 = fmaxf(m1, mx1);
        const float cr0 = ex2(m0 - mn0), cr1 = ex2(m1 - mn1);
        m0 = mn0; m1 = mn1;
        float rs0 = 0.f, rs1 = 0.f;
#pragma unroll
        for (int j = 0; j < 8; j++) {
            sf[j][0] = ex2(sf[j][0] - mn0); rs0 += sf[j][0];
            sf[j][1] = ex2(sf[j][1] - mn0); rs0 += sf[j][1];
            sf[j][2] = ex2(sf[j][2] - mn1); rs1 += sf[j][2];
            sf[j][3] = ex2(sf[j][3] - mn1); rs1 += sf[j][3];
        }
        rs0 += __shfl_xor_sync(0xffffffffu, rs0, 1);
        rs0 += __shfl_xor_sync(0xffffffffu, rs0, 2);
        rs1 += __shfl_xor_sync(0xffffffffu, rs1, 1);
        rs1 += __shfl_xor_sync(0xffffffffu, rs1, 2);
        l0 = l0 * cr0 + rs0;
        l1 = l1 * cr1 + rs1;
#pragma unroll
        for (int j = 0; j < 8; j++) {
            of[j][0] *= cr0; of[j][1] *= cr0;
            of[j][2] *= cr1; of[j][3] *= cr1;
        }

        // ---- pack P to bf16 hi/lo A-fragments (register-only remap) ----
        uint32_t ph[4][4], pl[4][4];
#pragma unroll
        for (int t = 0; t < 4; t++) {
#pragma unroll
            for (int q = 0; q < 4; q++) {
                const int j = 2 * t + (q >> 1);
                const int e = (q & 1) * 2;
                ph[t][q] = pack_hi(sf[j][e], sf[j][e + 1], pl[t][q]);
            }
        }

        // ---- O += P V (3 compensated terms) ----
        {
            const uint32_t colb = (lane >> 4) << 4;
#pragma unroll
            for (int t = 0; t < 4; t++) {
                uint32_t vh[4][4], vl[4][4];
                const int key = 16 * t + (lane & 7) + (((lane >> 3) & 1) << 3);
#pragma unroll
                for (int h = 0; h < 4; h++) {
                    const uint32_t a = base + (uint32_t)(key * 144 + h * 32) + colb;
                    ldm_x4_t(vh[h], a + OFF_VHI);
                    ldm_x4_t(vl[h], a + OFF_VLO);
                }
#pragma unroll
                for (int h = 0; h < 4; h++) {
                    mma_bf16(of[2 * h],     ph[t], vh[h][0], vh[h][1]);
                    mma_bf16(of[2 * h],     pl[t], vh[h][0], vh[h][1]);
                    mma_bf16(of[2 * h],     ph[t], vl[h][0], vl[h][1]);
                    mma_bf16(of[2 * h + 1], ph[t], vh[h][2], vh[h][3]);
                    mma_bf16(of[2 * h + 1], pl[t], vh[h][2], vh[h][3]);
                    mma_bf16(of[2 * h + 1], ph[t], vl[h][2], vl[h][3]);
                }
            }
        }
        __syncthreads();
    }

    // ---- normalize + store ----
    const float inv0 = 1.f / l0, inv1 = 1.f / l1;
    float* ob = out + ((size_t)b * SEQ + qbase + w * 16) * HEAD;
    const int r0 = lane >> 2, cb = 2 * (lane & 3);
#pragma unroll
    for (int j = 0; j < 8; j++) {
        *(float2*)&ob[(size_t)r0 * HEAD + 8 * j + cb] =
            make_float2(of[j][0] * inv0, of[j][1] * inv0);
        *(float2*)&ob[(size_t)(r0 + 8) * HEAD + 8 * j + cb] =
            make_float2(of[j][2] * inv1, of[j][3] * inv1);
    }
}

// ---------------------------------------------------------------------------
extern "C" void kernel_launch(void* const* d_in, const int* in_sizes, int n_in,
                              void* d_out, int out_size)
{
    (void)in_sizes; (void)n_in; (void)out_size;
    const float* emb = (const float*)d_in[0];
    const float* Wq  = (const float*)d_in[1];
    const float* Wk  = (const float*)d_in[2];
    const float* Wv  = (const float*)d_in[3];
    float* out = (float*)d_out;

    conv_w_kernel<<<(3 * HEAD * EMBED) / 256, 256>>>(Wq, Wk, Wv);

    cudaFuncSetAttribute(qkv_gemm_kernel, cudaFuncAttributeMaxDynamicSharedMemorySize,
                         GEMM_SMEM);
    qkv_gemm_kernel<<<(BATCH * SEQ) / 128, 256, GEMM_SMEM>>>(emb);

    cudaFuncSetAttribute(attn_kernel, cudaFuncAttributeMaxDynamicSharedMemorySize,
                         2 * AT_BUF);
    attn_kernel<<<256, 128, 2 * AT_BUF>>>(out);
}